// round 1
// baseline (speedup 1.0000x reference)
#include <cuda_runtime.h>
#include <cuda_bf16.h>
#include <cstdint>

// Problem constants
#define BATCH 128
#define NN    128           // nodes per graph
#define D_IN  6
#define HDIM  32
#define D_MP  64
#define TOTAL (BATCH*NN)    // 16384
#define U_STRIDE 512        // 4*N
#define U_PER_B  (512*512)  // 262144

__device__ float g_A0[TOTAL*128];   // h @ We0[:64]
__device__ float g_B0[TOTAL*128];   // h @ We0[64:]

__device__ __forceinline__ float lrelu(float v){ return v >= 0.f ? v : 0.1f*v; }

// ---------------------------------------------------------------------------
// K1: 3-layer GCN on complete graph. One block per batch, 128 threads = nodes.
// gcn(h,W,b)[n] = (S - (hW)[n])/127 + b, S = batch sum of hW.
// ---------------------------------------------------------------------------
__global__ void k1_gcn(const float* __restrict__ x,
                       const float* __restrict__ Wg0, const float* __restrict__ bg0,
                       const float* __restrict__ Wg1, const float* __restrict__ bg1,
                       const float* __restrict__ Wg2, const float* __restrict__ bg2,
                       float* __restrict__ h_out)
{
    __shared__ float buf[128*65];   // padded stride 65 (bank-conflict free)
    __shared__ float S[64];
    const int n = threadIdx.x;
    const int base = blockIdx.x * NN;
    const float inv = 1.0f/127.0f;

    float xr[D_IN];
#pragma unroll
    for (int k=0;k<D_IN;k++) xr[k] = x[(base+n)*D_IN + k];

    float y[64];

    // ---- layer 0: D_IN -> 32, lrelu ----
#pragma unroll
    for (int c=0;c<32;c++){
        float a = 0.f;
#pragma unroll
        for (int k=0;k<D_IN;k++) a += xr[k]*__ldg(&Wg0[k*32+c]);
        y[c]=a; buf[n*65+c]=a;
    }
    __syncthreads();
    if (n<32){ float s=0.f; for(int m=0;m<128;m++) s += buf[m*65+n]; S[n]=s; }
    __syncthreads();
#pragma unroll
    for (int c=0;c<32;c++) buf[n*65+c] = lrelu((S[c]-y[c])*inv + __ldg(&bg0[c]));
    __syncthreads();

    // ---- layer 1: 32 -> 32, lrelu ----
#pragma unroll
    for (int c=0;c<32;c++){
        float a = 0.f;
#pragma unroll
        for (int k=0;k<32;k++) a += buf[n*65+k]*__ldg(&Wg1[k*32+c]);
        y[c]=a;
    }
    __syncthreads();
#pragma unroll
    for (int c=0;c<32;c++) buf[n*65+c]=y[c];
    __syncthreads();
    if (n<32){ float s=0.f; for(int m=0;m<128;m++) s += buf[m*65+n]; S[n]=s; }
    __syncthreads();
#pragma unroll
    for (int c=0;c<32;c++) buf[n*65+c] = lrelu((S[c]-y[c])*inv + __ldg(&bg1[c]));
    __syncthreads();

    // ---- layer 2: 32 -> 64, no activation ----
#pragma unroll
    for (int c=0;c<64;c++){
        float a = 0.f;
#pragma unroll
        for (int k=0;k<32;k++) a += buf[n*65+k]*__ldg(&Wg2[k*64+c]);
        y[c]=a;
    }
    __syncthreads();
#pragma unroll
    for (int c=0;c<64;c++) buf[n*65+c]=y[c];
    __syncthreads();
    if (n<64){ float s=0.f; for(int m=0;m<128;m++) s += buf[m*65+n]; S[n]=s; }
    __syncthreads();
#pragma unroll
    for (int c=0;c<64;c++)
        h_out[(base+n)*64 + c] = (S[c]-y[c])*inv + __ldg(&bg2[c]);
}

// ---------------------------------------------------------------------------
// K2: A0 = h @ We0[:64,:], B0 = h @ We0[64:,:].  Block: 32 nodes, 256 threads
// (thread = output column; 128 A-cols then 128 B-cols).
// ---------------------------------------------------------------------------
__global__ void k2_ab(const float* __restrict__ h, const float* __restrict__ We0)
{
    __shared__ float hs[32*64];
    const int tid = threadIdx.x;
    const int n0 = blockIdx.x * 32;

    for (int l = tid; l < 32*64; l += 256) hs[l] = h[n0*64 + l];
    __syncthreads();

    const int col = tid & 127;
    const int kb  = (tid >> 7) * 64;   // 0 -> A0 (rows 0..63), 1 -> B0 (rows 64..127)

    float acc[32];
#pragma unroll
    for (int i=0;i<32;i++) acc[i]=0.f;

    for (int k=0;k<64;k++){
        float w = __ldg(&We0[(kb+k)*128 + col]);
#pragma unroll
        for (int nn=0;nn<32;nn++) acc[nn] += hs[nn*64+k]*w;   // broadcast LDS
    }

    float* dst = (tid < 128) ? g_A0 : g_B0;
#pragma unroll
    for (int nn=0;nn<32;nn++) dst[(size_t)(n0+nn)*128 + col] = acc[nn];
}

// ---------------------------------------------------------------------------
// K2b: node MLP 64->64->64->10 + diagonal 4x4 blocks of U.
// One block per batch, thread = node, weights staged in shared.
// ---------------------------------------------------------------------------
__global__ void k2b_node(const float* __restrict__ h,
                         const float* __restrict__ Wn0, const float* __restrict__ bn0,
                         const float* __restrict__ Wn1, const float* __restrict__ bn1,
                         const float* __restrict__ Wn2, const float* __restrict__ bn2,
                         float* __restrict__ U)
{
    __shared__ float w0[64*64], w1[64*64], w2[64*10];
    __shared__ float b0s[64], b1s[64], b2s[10];
    const int n = threadIdx.x;
    const int b = blockIdx.x;

    for (int l=n; l<4096; l+=128){ w0[l]=Wn0[l]; w1[l]=Wn1[l]; }
    for (int l=n; l<640;  l+=128) w2[l]=Wn2[l];
    if (n<64){ b0s[n]=bn0[n]; b1s[n]=bn1[n]; }
    if (n<10) b2s[n]=bn2[n];
    __syncthreads();

    const float* hr = h + (size_t)(b*NN+n)*64;
    float h0[64];
#pragma unroll
    for (int k=0;k<64;k++) h0[k]=hr[k];

    float t1[64];
#pragma unroll
    for (int c=0;c<64;c++){
        float a=b0s[c];
#pragma unroll
        for (int k=0;k<64;k++) a += h0[k]*w0[k*64+c];
        t1[c]=lrelu(a);
    }
    float t2[64];
#pragma unroll
    for (int c=0;c<64;c++){
        float a=b1s[c];
#pragma unroll
        for (int k=0;k<64;k++) a += t1[k]*w1[k*64+c];
        t2[c]=lrelu(a);
    }
    float v[10];
#pragma unroll
    for (int c=0;c<10;c++){
        float a=b2s[c];
#pragma unroll
        for (int k=0;k<64;k++) a += t2[k]*w2[k*10+c];
        v[c]=a;
    }

    const int SMAT[16] = {0,1,2,3, 1,4,5,6, 2,5,7,8, 3,6,8,9};
    float* Ub = U + (size_t)b*U_PER_B;
#pragma unroll
    for (int a=0;a<4;a++){
        float4 r;
        r.x = v[SMAT[a*4+0]]; r.y = v[SMAT[a*4+1]];
        r.z = v[SMAT[a*4+2]]; r.w = v[SMAT[a*4+3]];
        *reinterpret_cast<float4*>(Ub + (size_t)(4*n+a)*U_STRIDE + 4*n) = r;
    }
}

// ---------------------------------------------------------------------------
// K3: edge MLP (layers 1,2 per-pair) + scatter into U off-diagonal blocks.
// Grid (16,16,128): blockIdx.y = i-tile, blockIdx.x = j-tile, z = batch.
// 8x8 pair tile (64 pairs), 256 threads, shared-memory GEMMs.
// ---------------------------------------------------------------------------
#define K3_SMEM_FLOATS (2*64*130 + 32*132)
#define K3_SMEM_BYTES  (K3_SMEM_FLOATS*4)

__global__ void k3_edge(const float* __restrict__ be0,
                        const float* __restrict__ We1, const float* __restrict__ be1,
                        const float* __restrict__ We2, const float* __restrict__ be2,
                        float* __restrict__ U)
{
    if (blockIdx.y > blockIdx.x) return;   // only i-tile <= j-tile

    extern __shared__ float smem[];
    float* t0s = smem;                 // [64][130]
    float* t1s = smem + 64*130;        // [64][130]
    float* ws  = smem + 2*64*130;      // [32][132] staging / We2
    float* A0s = t1s;                  // alias (t1s unused until epilogue)
    float* B0s = t1s + 8*128;

    const int tid = threadIdx.x;
    const int b  = blockIdx.z;
    const int i0 = blockIdx.y * 8;
    const int j0 = blockIdx.x * 8;

    // ---- stage A0 (8 rows) and B0 (8 rows) ----
#pragma unroll
    for (int l = tid; l < 512; l += 256){            // 512 float4s
        int half = l >> 8;                           // 0: A0, 1: B0
        int r = (l >> 5) & 7, c4 = l & 31;
        const float* src = half ? (g_B0 + (size_t)(b*NN + j0 + r)*128)
                                : (g_A0 + (size_t)(b*NN + i0 + r)*128);
        float4 v = *reinterpret_cast<const float4*>(src + c4*4);
        float* dst = half ? B0s : A0s;
        *reinterpret_cast<float4*>(dst + r*128 + c4*4) = v;
    }
    __syncthreads();

    // ---- t0[p][k] = lrelu(A0[i] + B0[j] + be0) ----
#pragma unroll
    for (int e = tid; e < 64*128; e += 256){
        int p = e >> 7, k = e & 127;
        int ii = p >> 3, jj = p & 7;
        t0s[p*130 + k] = lrelu(A0s[ii*128+k] + B0s[jj*128+k] + __ldg(&be0[k]));
    }
    __syncthreads();

    // ---- GEMM1: t1 = lrelu(t0[64x128] @ We1[128x128] + be1) ----
    const int tr = tid >> 4;      // 0..15 -> rows tr*4..+3
    const int tc = tid & 15;      // 0..15 -> cols tc*8..+7
    float acc[4][8];
#pragma unroll
    for (int r=0;r<4;r++)
#pragma unroll
        for (int c=0;c<8;c++) acc[r][c]=0.f;

    for (int kb = 0; kb < 128; kb += 32){
#pragma unroll
        for (int l = tid; l < 1024; l += 256){       // 32 rows x 32 float4
            int r = l >> 5, c4 = l & 31;
            float4 w = *reinterpret_cast<const float4*>(We1 + (size_t)(kb+r)*128 + c4*4);
            *reinterpret_cast<float4*>(ws + r*132 + c4*4) = w;
        }
        __syncthreads();
#pragma unroll 8
        for (int kk = 0; kk < 32; ++kk){
            float a[4];
#pragma unroll
            for (int r=0;r<4;r++) a[r] = t0s[(tr*4+r)*130 + kb + kk];
            float4 bv0 = *reinterpret_cast<const float4*>(ws + kk*132 + tc*8);
            float4 bv1 = *reinterpret_cast<const float4*>(ws + kk*132 + tc*8 + 4);
            float bvf[8] = {bv0.x,bv0.y,bv0.z,bv0.w, bv1.x,bv1.y,bv1.z,bv1.w};
#pragma unroll
            for (int r=0;r<4;r++)
#pragma unroll
                for (int c=0;c<8;c++) acc[r][c] += a[r]*bvf[c];
        }
        __syncthreads();
    }
#pragma unroll
    for (int r=0;r<4;r++){
        int row = tr*4+r;
#pragma unroll
        for (int c=0;c<8;c++){
            int col = tc*8+c;
            t1s[row*130+col] = lrelu(acc[r][c] + __ldg(&be1[col]));
        }
    }
    // stage We2 into ws (linear [128*16])
#pragma unroll
    for (int l = tid; l < 128*16; l += 256) ws[l] = __ldg(&We2[l]);
    __syncthreads();

    // ---- GEMM2 + scatter: e = t1 @ We2 + be2; 4 threads per pair ----
    const int p = tid >> 2;     // pair 0..63
    const int q = tid & 3;      // row of 4x4 block
    float4 e = *reinterpret_cast<const float4*>(be2 + q*4);
#pragma unroll 8
    for (int k = 0; k < 128; ++k){
        float v = t1s[p*130 + k];
        float4 w = *reinterpret_cast<const float4*>(ws + k*16 + q*4);
        e.x += v*w.x; e.y += v*w.y; e.z += v*w.z; e.w += v*w.w;
    }
    const int i = i0 + (p >> 3);
    const int j = j0 + (p & 7);
    if (i < j){
        float* Ub = U + (size_t)b*U_PER_B;
        *reinterpret_cast<float4*>(Ub + (size_t)(4*i+q)*U_STRIDE + 4*j) = e;
        *reinterpret_cast<float4*>(Ub + (size_t)(4*j+q)*U_STRIDE + 4*i) = e;
    }
}

// ---------------------------------------------------------------------------
extern "C" void kernel_launch(void* const* d_in, const int* in_sizes, int n_in,
                              void* d_out, int out_size)
{
    const float* x   = (const float*)d_in[0];
    // d_in[1]=edge_index, d_in[2]=edge_map, d_in[3]=ud_edges: structure is the
    // known complete graph; not needed at runtime.
    const float* Wg0 = (const float*)d_in[4];
    const float* bg0 = (const float*)d_in[5];
    const float* Wg1 = (const float*)d_in[6];
    const float* bg1 = (const float*)d_in[7];
    const float* Wg2 = (const float*)d_in[8];
    const float* bg2 = (const float*)d_in[9];
    const float* Wn0 = (const float*)d_in[10];
    const float* bn0 = (const float*)d_in[11];
    const float* Wn1 = (const float*)d_in[12];
    const float* bn1 = (const float*)d_in[13];
    const float* Wn2 = (const float*)d_in[14];
    const float* bn2 = (const float*)d_in[15];
    const float* We0 = (const float*)d_in[16];
    const float* be0 = (const float*)d_in[17];
    const float* We1 = (const float*)d_in[18];
    const float* be1 = (const float*)d_in[19];
    const float* We2 = (const float*)d_in[20];
    const float* be2 = (const float*)d_in[21];

    float* h_out = (float*)d_out;                     // (16384, 64)
    float* U     = h_out + (size_t)TOTAL*D_MP;        // (128, 512, 512)

    cudaFuncSetAttribute(k3_edge, cudaFuncAttributeMaxDynamicSharedMemorySize,
                         K3_SMEM_BYTES);

    k1_gcn<<<BATCH, 128>>>(x, Wg0,bg0, Wg1,bg1, Wg2,bg2, h_out);
    k2_ab<<<TOTAL/32, 256>>>(h_out, We0);
    k2b_node<<<BATCH, 128>>>(h_out, Wn0,bn0, Wn1,bn1, Wn2,bn2, U);
    k3_edge<<<dim3(16,16,BATCH), 256, K3_SMEM_BYTES>>>(be0, We1, be1, We2, be2, U);
}